// round 1
// baseline (speedup 1.0000x reference)
#include <cuda_runtime.h>
#include <math.h>

#define NN 50000
#define NE 800000
#define NG 64

// ---------------- scratch (static __device__, no allocs) ----------------
__device__ __align__(16) float d_zb[NN * 128];    // [base(64) | z(64)] per node
__device__ __align__(16) float d_aggr[NN * 256];  // [mean|min|max|std]
__device__ __align__(16) float d_xa[NN * 64];
__device__ __align__(16) float d_xb[NN * 64];
__device__ int   d_deg[NN];
__device__ int   d_off[NN + 1];
__device__ int   d_cur[NN];
__device__ int   d_csr[NE];
__device__ float d_amp[NN];
__device__ float d_att[NN];
__device__ float d_avglog;
__device__ float d_pool[NG * 64];
__device__ int   d_cnt[NG];

// ---------------- setup kernels ----------------
__global__ void k_init() {
    int i = blockIdx.x * blockDim.x + threadIdx.x;
    if (i < NN) d_deg[i] = 0;
    if (i < NG * 64) d_pool[i] = 0.f;
    if (i < NG) d_cnt[i] = 0;
}

__global__ void k_degree(const int* __restrict__ dst) {
    int e = blockIdx.x * blockDim.x + threadIdx.x;
    if (e < NE) atomicAdd(&d_deg[dst[e]], 1);
}

// single-block exclusive scan of d_deg -> d_off/d_cur, plus avg-log-degree
__global__ void k_scan() {
    __shared__ int s_warp[32];
    __shared__ int s_tot;
    __shared__ int s_base;
    __shared__ float s_log[32];
    int tid = threadIdx.x, lane = tid & 31, wid = tid >> 5;
    if (tid == 0) s_base = 0;
    float lsum = 0.f;
    __syncthreads();
    for (int start = 0; start < NN; start += 1024) {
        int i = start + tid;
        int v = (i < NN) ? d_deg[i] : 0;
        if (i < NN) lsum += logf((float)v + 1.f);
        int x = v;
        #pragma unroll
        for (int d = 1; d < 32; d <<= 1) {
            int t = __shfl_up_sync(0xffffffffu, x, d);
            if (lane >= d) x += t;
        }
        if (lane == 31) s_warp[wid] = x;
        __syncthreads();
        if (wid == 0) {
            int ws = s_warp[lane];
            int y = ws;
            #pragma unroll
            for (int d = 1; d < 32; d <<= 1) {
                int t = __shfl_up_sync(0xffffffffu, y, d);
                if (lane >= d) y += t;
            }
            s_warp[lane] = y - ws;
            if (lane == 31) s_tot = y;
        }
        __syncthreads();
        int excl = s_base + s_warp[wid] + (x - v);
        if (i < NN) { d_off[i] = excl; d_cur[i] = excl; }
        __syncthreads();
        if (tid == 0) s_base += s_tot;
        __syncthreads();
    }
    if (tid == 0) d_off[NN] = s_base;
    #pragma unroll
    for (int d = 16; d; d >>= 1) lsum += __shfl_xor_sync(0xffffffffu, lsum, d);
    if (lane == 0) s_log[wid] = lsum;
    __syncthreads();
    if (tid == 0) {
        float t = 0.f;
        for (int w = 0; w < 32; w++) t += s_log[w];
        d_avglog = t / (float)NN;
    }
}

__global__ void k_fill(const int* __restrict__ src, const int* __restrict__ dst) {
    int e = blockIdx.x * blockDim.x + threadIdx.x;
    if (e < NE) {
        int dn = dst[e];
        int p = atomicAdd(&d_cur[dn], 1);
        d_csr[p] = src[e];
    }
}

__global__ void k_scalars() {
    int i = blockIdx.x * blockDim.x + threadIdx.x;
    if (i >= NN) return;
    float avg = d_avglog;
    int d = d_deg[i];
    float degf = (float)(d > 1 ? d : 1);
    float ld = logf(degf + 1.f);
    d_amp[i] = ld / avg;
    d_att[i] = avg / ld;
}

// ---------------- pre GEMM: [32 rows] x [64 -> 128]  (base|z) ----------------
__global__ __launch_bounds__(256) void k_pre(const float* __restrict__ X,
                                             const float* __restrict__ W,
                                             const float* __restrict__ B) {
    __shared__ float Xs[64][33];   // [k][row]
    __shared__ float Ws[64][132];  // [k][j]
    __shared__ float bs[64];
    int tid = threadIdx.x;
    int row0 = blockIdx.x * 32;
    for (int i = tid; i < 512; i += 256) {   // 32 rows * 16 float4
        int r = i >> 4, kv = i & 15;
        int gr = row0 + r;
        float4 v = make_float4(0.f, 0.f, 0.f, 0.f);
        if (gr < NN) v = *(const float4*)(X + (size_t)gr * 64 + kv * 4);
        Xs[kv*4+0][r] = v.x; Xs[kv*4+1][r] = v.y; Xs[kv*4+2][r] = v.z; Xs[kv*4+3][r] = v.w;
    }
    for (int i = tid; i < 8192; i += 256) {  // remap pre_w[64,128] -> Ws[k][j]
        int j = i >> 6, k = i & 63;
        Ws[k][j] = (j < 64) ? W[j * 128 + k] : W[(j - 64) * 128 + 64 + k];
    }
    if (tid < 64) bs[tid] = B[tid];
    __syncthreads();
    int tx = tid & 15, ty = tid >> 4;  // tx -> 8 cols, ty -> 2 rows
    float acc[2][8];
    #pragma unroll
    for (int r = 0; r < 2; r++)
        #pragma unroll
        for (int j = 0; j < 8; j++) acc[r][j] = 0.f;
    #pragma unroll 4
    for (int k = 0; k < 64; k++) {
        float a0 = Xs[k][ty * 2 + 0];
        float a1 = Xs[k][ty * 2 + 1];
        float4 w0 = *(const float4*)&Ws[k][tx * 8];
        float4 w1 = *(const float4*)&Ws[k][tx * 8 + 4];
        float w[8] = {w0.x, w0.y, w0.z, w0.w, w1.x, w1.y, w1.z, w1.w};
        #pragma unroll
        for (int j = 0; j < 8; j++) { acc[0][j] += a0 * w[j]; acc[1][j] += a1 * w[j]; }
    }
    int j0 = tx * 8;
    #pragma unroll
    for (int r = 0; r < 2; r++) {
        int gr = row0 + ty * 2 + r;
        if (gr >= NN) continue;
        float o[8];
        #pragma unroll
        for (int j = 0; j < 8; j++) o[j] = acc[r][j] + ((j0 < 64) ? bs[j0 + j] : 0.f);
        *(float4*)(d_zb + (size_t)gr * 128 + j0) = make_float4(o[0], o[1], o[2], o[3]);
        *(float4*)(d_zb + (size_t)gr * 128 + j0 + 4) = make_float4(o[4], o[5], o[6], o[7]);
    }
}

// ---------------- aggregation: 1 warp per node ----------------
__global__ __launch_bounds__(256) void k_aggr() {
    int gw = (blockIdx.x * blockDim.x + threadIdx.x) >> 5;
    int lane = threadIdx.x & 31;
    if (gw >= NN) return;
    int beg = d_off[gw], end = d_off[gw + 1];
    float2 base = *(const float2*)(d_zb + (size_t)gw * 128 + lane * 2);
    float s1x = 0.f, s1y = 0.f, s2x = 0.f, s2y = 0.f;
    float mnx = INFINITY, mny = INFINITY, mxx = -INFINITY, mxy = -INFINITY;
    int e = beg;
    for (; e + 4 <= end; e += 4) {
        int i0 = d_csr[e], i1 = d_csr[e + 1], i2 = d_csr[e + 2], i3 = d_csr[e + 3];
        float2 z0 = *(const float2*)(d_zb + (size_t)i0 * 128 + 64 + lane * 2);
        float2 z1 = *(const float2*)(d_zb + (size_t)i1 * 128 + 64 + lane * 2);
        float2 z2 = *(const float2*)(d_zb + (size_t)i2 * 128 + 64 + lane * 2);
        float2 z3 = *(const float2*)(d_zb + (size_t)i3 * 128 + 64 + lane * 2);
        float mx0 = base.x + z0.x, my0 = base.y + z0.y;
        float mx1 = base.x + z1.x, my1 = base.y + z1.y;
        float mx2 = base.x + z2.x, my2 = base.y + z2.y;
        float mx3 = base.x + z3.x, my3 = base.y + z3.y;
        s1x += mx0 + mx1 + mx2 + mx3;
        s1y += my0 + my1 + my2 + my3;
        s2x += mx0*mx0 + mx1*mx1 + mx2*mx2 + mx3*mx3;
        s2y += my0*my0 + my1*my1 + my2*my2 + my3*my3;
        mnx = fminf(mnx, fminf(fminf(mx0, mx1), fminf(mx2, mx3)));
        mny = fminf(mny, fminf(fminf(my0, my1), fminf(my2, my3)));
        mxx = fmaxf(mxx, fmaxf(fmaxf(mx0, mx1), fmaxf(mx2, mx3)));
        mxy = fmaxf(mxy, fmaxf(fmaxf(my0, my1), fmaxf(my2, my3)));
    }
    for (; e < end; e++) {
        int s = d_csr[e];
        float2 z = *(const float2*)(d_zb + (size_t)s * 128 + 64 + lane * 2);
        float mx_ = base.x + z.x, my_ = base.y + z.y;
        s1x += mx_; s2x += mx_ * mx_; mnx = fminf(mnx, mx_); mxx = fmaxf(mxx, mx_);
        s1y += my_; s2y += my_ * my_; mny = fminf(mny, my_); mxy = fmaxf(mxy, my_);
    }
    int drI = end - beg;
    float deg = (float)(drI > 0 ? drI : 1);
    float meanx = s1x / deg, meany = s1y / deg;
    float stdx = sqrtf(fmaxf(s2x / deg - meanx * meanx, 0.f) + 1e-5f);
    float stdy = sqrtf(fmaxf(s2y / deg - meany * meany, 0.f) + 1e-5f);
    if (drI == 0) { mnx = 0.f; mny = 0.f; mxx = 0.f; mxy = 0.f; }
    float* a = d_aggr + (size_t)gw * 256;
    *(float2*)(a + lane * 2)       = make_float2(meanx, meany);
    *(float2*)(a + 64 + lane * 2)  = make_float2(mnx, mny);
    *(float2*)(a + 128 + lane * 2) = make_float2(mxx, mxy);
    *(float2*)(a + 192 + lane * 2) = make_float2(stdx, stdy);
}

// ---------------- post(832->64) + lin(64->64) + relu, fused, 64 rows/block ----------------
__global__ __launch_bounds__(256) void k_post(const float* __restrict__ X,
                                              const float* __restrict__ Wp,
                                              const float* __restrict__ bp,
                                              const float* __restrict__ Wl,
                                              const float* __restrict__ bl,
                                              float* __restrict__ Xn) {
    __shared__ float As[64][65];   // [k][row]
    __shared__ float Ws[64][68];   // [k][j]
    int tid = threadIdx.x;
    int row0 = blockIdx.x * 64;
    int tx = tid & 15, ty = tid >> 4;  // tx -> 4 cols, ty -> 4 rows
    float acc[4][4];
    #pragma unroll
    for (int r = 0; r < 4; r++)
        #pragma unroll
        for (int c = 0; c < 4; c++) acc[r][c] = 0.f;

    for (int c = 0; c < 13; c++) {
        __syncthreads();
        // A chunk: c==0 -> x; 1..4 -> aggr; 5..8 -> aggr*amp; 9..12 -> aggr*att
        for (int i = tid; i < 1024; i += 256) {
            int r = i >> 4, kv = i & 15;
            int gr = row0 + r;
            float4 v = make_float4(0.f, 0.f, 0.f, 0.f);
            if (gr < NN) {
                if (c == 0) {
                    v = *(const float4*)(X + (size_t)gr * 64 + kv * 4);
                } else {
                    int cc = c - 1;
                    v = *(const float4*)(d_aggr + (size_t)gr * 256 + (cc & 3) * 64 + kv * 4);
                    if (cc >= 8)      { float s = d_att[gr]; v.x *= s; v.y *= s; v.z *= s; v.w *= s; }
                    else if (cc >= 4) { float s = d_amp[gr]; v.x *= s; v.y *= s; v.z *= s; v.w *= s; }
                }
            }
            As[kv*4+0][r] = v.x; As[kv*4+1][r] = v.y; As[kv*4+2][r] = v.z; As[kv*4+3][r] = v.w;
        }
        for (int i = tid; i < 4096; i += 256) {
            int j = i >> 6, k = i & 63;
            Ws[k][j] = Wp[(size_t)j * 832 + c * 64 + k];
        }
        __syncthreads();
        #pragma unroll 4
        for (int k = 0; k < 64; k++) {
            float a0 = As[k][ty*4+0], a1 = As[k][ty*4+1], a2 = As[k][ty*4+2], a3 = As[k][ty*4+3];
            float4 w = *(const float4*)&Ws[k][tx * 4];
            acc[0][0] += a0*w.x; acc[0][1] += a0*w.y; acc[0][2] += a0*w.z; acc[0][3] += a0*w.w;
            acc[1][0] += a1*w.x; acc[1][1] += a1*w.y; acc[1][2] += a1*w.z; acc[1][3] += a1*w.w;
            acc[2][0] += a2*w.x; acc[2][1] += a2*w.y; acc[2][2] += a2*w.z; acc[2][3] += a2*w.w;
            acc[3][0] += a3*w.x; acc[3][1] += a3*w.y; acc[3][2] += a3*w.z; acc[3][3] += a3*w.w;
        }
    }
    __syncthreads();
    // stage post output transposed into As, add bias
    #pragma unroll
    for (int r = 0; r < 4; r++)
        #pragma unroll
        for (int cj = 0; cj < 4; cj++)
            As[tx * 4 + cj][ty * 4 + r] = acc[r][cj] + bp[tx * 4 + cj];
    for (int i = tid; i < 4096; i += 256) {
        int j = i >> 6, k = i & 63;
        Ws[k][j] = Wl[j * 64 + k];
    }
    __syncthreads();
    float acc2[4][4];
    #pragma unroll
    for (int r = 0; r < 4; r++)
        #pragma unroll
        for (int c = 0; c < 4; c++) acc2[r][c] = 0.f;
    #pragma unroll 4
    for (int k = 0; k < 64; k++) {
        float a0 = As[k][ty*4+0], a1 = As[k][ty*4+1], a2 = As[k][ty*4+2], a3 = As[k][ty*4+3];
        float4 w = *(const float4*)&Ws[k][tx * 4];
        acc2[0][0] += a0*w.x; acc2[0][1] += a0*w.y; acc2[0][2] += a0*w.z; acc2[0][3] += a0*w.w;
        acc2[1][0] += a1*w.x; acc2[1][1] += a1*w.y; acc2[1][2] += a1*w.z; acc2[1][3] += a1*w.w;
        acc2[2][0] += a2*w.x; acc2[2][1] += a2*w.y; acc2[2][2] += a2*w.z; acc2[2][3] += a2*w.w;
        acc2[3][0] += a3*w.x; acc2[3][1] += a3*w.y; acc2[3][2] += a3*w.z; acc2[3][3] += a3*w.w;
    }
    #pragma unroll
    for (int r = 0; r < 4; r++) {
        int gr = row0 + ty * 4 + r;
        if (gr < NN) {
            float4 o;
            o.x = fmaxf(acc2[r][0] + bl[tx*4+0], 0.f);
            o.y = fmaxf(acc2[r][1] + bl[tx*4+1], 0.f);
            o.z = fmaxf(acc2[r][2] + bl[tx*4+2], 0.f);
            o.w = fmaxf(acc2[r][3] + bl[tx*4+3], 0.f);
            *(float4*)(Xn + (size_t)gr * 64 + tx * 4) = o;
        }
    }
}

// ---------------- pooling (sorted batch, 8-node local pre-aggregation) ----------------
__global__ void k_pool(const float* __restrict__ X, const int* __restrict__ batch) {
    int idx = blockIdx.x * blockDim.x + threadIdx.x;
    int f = idx & 63;
    int chunk = idx >> 6;
    int n0 = chunk * 8;
    if (n0 >= NN) return;
    int ne = n0 + 8 < NN ? n0 + 8 : NN;
    int cg = batch[n0];
    float acc = 0.f;
    int cnt = 0;
    for (int n = n0; n < ne; n++) {
        int g = batch[n];
        if (g != cg) {
            atomicAdd(&d_pool[cg * 64 + f], acc);
            if (f == 0) atomicAdd(&d_cnt[cg], cnt);
            acc = 0.f; cnt = 0; cg = g;
        }
        acc += X[(size_t)n * 64 + f];
        cnt++;
    }
    atomicAdd(&d_pool[cg * 64 + f], acc);
    if (f == 0) atomicAdd(&d_cnt[cg], cnt);
}

__global__ void k_mlp(const float* __restrict__ W1, const float* __restrict__ b1,
                      const float* __restrict__ W2, const float* __restrict__ b2,
                      float* __restrict__ out) {
    __shared__ float gv[64], hv[64];
    int g = blockIdx.x, t = threadIdx.x;
    int c = d_cnt[g];
    float cntf = (float)(c > 1 ? c : 1);
    gv[t] = d_pool[g * 64 + t] / cntf;
    __syncthreads();
    float a = b1[t];
    #pragma unroll 8
    for (int k = 0; k < 64; k++) a += W1[t * 64 + k] * gv[k];
    hv[t] = fmaxf(a, 0.f);
    __syncthreads();
    if (t < 16) {
        float o = b2[t];
        #pragma unroll 8
        for (int k = 0; k < 64; k++) o += W2[t * 64 + k] * hv[k];
        out[g * 16 + t] = o;
    }
}

// ---------------- launch ----------------
extern "C" void kernel_launch(void* const* d_in, const int* in_sizes, int n_in,
                              void* d_out, int out_size) {
    const float* x      = (const float*)d_in[0];
    const int*   ei     = (const int*)d_in[1];
    const int*   batch  = (const int*)d_in[2];
    const float* pre_w  = (const float*)d_in[3];
    const float* pre_b  = (const float*)d_in[4];
    const float* post_w = (const float*)d_in[5];
    const float* post_b = (const float*)d_in[6];
    const float* lin_w  = (const float*)d_in[7];
    const float* lin_b  = (const float*)d_in[8];
    const float* mw1    = (const float*)d_in[9];
    const float* mb1    = (const float*)d_in[10];
    const float* mw2    = (const float*)d_in[11];
    const float* mb2    = (const float*)d_in[12];
    float* out = (float*)d_out;
    const int* srcp = ei;
    const int* dstp = ei + NE;

    void *pa, *pb;
    cudaGetSymbolAddress(&pa, d_xa);
    cudaGetSymbolAddress(&pb, d_xb);
    float* xa = (float*)pa;
    float* xb = (float*)pb;

    k_init<<<(NN + 255) / 256, 256>>>();
    k_degree<<<(NE + 255) / 256, 256>>>(dstp);
    k_scan<<<1, 1024>>>();
    k_fill<<<(NE + 255) / 256, 256>>>(srcp, dstp);
    k_scalars<<<(NN + 255) / 256, 256>>>();

    const float* cur = x;
    float* nxt = xa;
    for (int l = 0; l < 3; l++) {
        k_pre<<<(NN + 31) / 32, 256>>>(cur, pre_w + l * 64 * 128, pre_b + l * 64);
        k_aggr<<<(NN * 32 + 255) / 256, 256>>>();
        k_post<<<(NN + 63) / 64, 256>>>(cur, post_w + (size_t)l * 64 * 832, post_b + l * 64,
                                        lin_w + l * 64 * 64, lin_b + l * 64, nxt);
        cur = nxt;
        nxt = (nxt == xa) ? xb : xa;
    }
    k_pool<<<(((NN + 7) / 8) * 64 + 255) / 256, 256>>>(cur, batch);
    k_mlp<<<NG, 64>>>(mw1, mb1, mw2, mb2, out);
}

// round 5
// speedup vs baseline: 1.4677x; 1.4677x over previous
#include <cuda_runtime.h>
#include <cstdint>
#include <math.h>

#define NN 50000
#define NE 800000
#define NG 64
#define NB_SCAN 196   // ceil(NN/256)

// ---------------- scratch (static __device__, no allocs) ----------------
__device__ __align__(16) float d_zb[NN * 128];    // [base(64) | z(64)] per node
__device__ __align__(16) float d_aggr[NN * 256];  // [mean|min|max|std]
__device__ __align__(16) float d_xa[NN * 64];
__device__ __align__(16) float d_xb[NN * 64];
__device__ int   d_deg[NN];
__device__ int   d_off[NN + 1];
__device__ int   d_cur[NN];
__device__ int   d_csr[NE];
__device__ float d_amp[NN];
__device__ float d_att[NN];
__device__ float d_avglog;
__device__ float d_pool[NG * 64];
__device__ int   d_cnt[NG];
__device__ int   d_part[NB_SCAN];
__device__ float d_logpart[NB_SCAN];
__device__ int   d_boff[NB_SCAN];

// ---------------- mma.sync tf32 helpers (sm_80+ baseline PTX) ----------
__device__ __forceinline__ uint32_t f2tf(float x) {
    uint32_t u;
    asm("cvt.rna.tf32.f32 %0, %1;" : "=r"(u) : "f"(x));
    return u;
}

// 3xTF32 split: v = hi + lo (hi,lo both tf32-representable)
__device__ __forceinline__ void tf32_split(float v, uint32_t& hi, uint32_t& lo) {
    uint32_t h = f2tf(v);
    hi = h;
    lo = f2tf(v - __uint_as_float(h));
}

__device__ __forceinline__ void mma_tf32(float& c0, float& c1, float& c2, float& c3,
                                         uint32_t a0, uint32_t a1, uint32_t a2, uint32_t a3,
                                         uint32_t b0, uint32_t b1) {
    asm volatile("mma.sync.aligned.m16n8k8.row.col.f32.tf32.tf32.f32 "
        "{%0,%1,%2,%3}, {%4,%5,%6,%7}, {%8,%9}, {%0,%1,%2,%3};"
        : "+f"(c0), "+f"(c1), "+f"(c2), "+f"(c3)
        : "r"(a0), "r"(a1), "r"(a2), "r"(a3), "r"(b0), "r"(b1));
}

// ---------------- setup kernels ----------------
__global__ void k_init() {
    int i = blockIdx.x * blockDim.x + threadIdx.x;
    if (i < NN) d_deg[i] = 0;
    if (i < NG * 64) d_pool[i] = 0.f;
    if (i < NG) d_cnt[i] = 0;
}

__global__ void k_degree(const int* __restrict__ dst) {
    int e = blockIdx.x * blockDim.x + threadIdx.x;
    if (e < NE) atomicAdd(&d_deg[dst[e]], 1);
}

__global__ void k_scan1() {
    __shared__ int ssum[8];
    __shared__ float slog[8];
    int tid = threadIdx.x, lane = tid & 31, w = tid >> 5;
    int i = blockIdx.x * 256 + tid;
    int v = (i < NN) ? d_deg[i] : 0;
    float l = (i < NN) ? logf((float)v + 1.f) : 0.f;
    int s = v;
    #pragma unroll
    for (int d = 16; d; d >>= 1) {
        s += __shfl_xor_sync(0xffffffffu, s, d);
        l += __shfl_xor_sync(0xffffffffu, l, d);
    }
    if (lane == 0) { ssum[w] = s; slog[w] = l; }
    __syncthreads();
    if (tid == 0) {
        int t = 0; float lt = 0.f;
        #pragma unroll
        for (int k = 0; k < 8; k++) { t += ssum[k]; lt += slog[k]; }
        d_part[blockIdx.x] = t;
        d_logpart[blockIdx.x] = lt;
    }
}

__global__ void k_scan2() {
    __shared__ int ws[8];
    int tid = threadIdx.x, lane = tid & 31, w = tid >> 5;
    int v = (tid < NB_SCAN) ? d_part[tid] : 0;
    int x = v;
    #pragma unroll
    for (int d = 1; d < 32; d <<= 1) {
        int t = __shfl_up_sync(0xffffffffu, x, d);
        if (lane >= d) x += t;
    }
    if (lane == 31) ws[w] = x;
    __syncthreads();
    if (tid == 0) {
        int acc = 0;
        #pragma unroll
        for (int k = 0; k < 8; k++) { int t = ws[k]; ws[k] = acc; acc += t; }
    }
    __syncthreads();
    int excl = ws[w] + x - v;
    if (tid < NB_SCAN) d_boff[tid] = excl;
    if (tid == 0) {
        d_off[NN] = NE;
        float s = 0.f;
        for (int k = 0; k < NB_SCAN; k++) s += d_logpart[k];
        d_avglog = s / (float)NN;
    }
}

__global__ void k_scan3() {
    __shared__ int ws[8];
    int tid = threadIdx.x, lane = tid & 31, w = tid >> 5;
    int i = blockIdx.x * 256 + tid;
    int v = (i < NN) ? d_deg[i] : 0;
    int x = v;
    #pragma unroll
    for (int d = 1; d < 32; d <<= 1) {
        int t = __shfl_up_sync(0xffffffffu, x, d);
        if (lane >= d) x += t;
    }
    if (lane == 31) ws[w] = x;
    __syncthreads();
    if (tid == 0) {
        int acc = 0;
        #pragma unroll
        for (int k = 0; k < 8; k++) { int t = ws[k]; ws[k] = acc; acc += t; }
    }
    __syncthreads();
    int excl = d_boff[blockIdx.x] + ws[w] + x - v;
    if (i < NN) {
        d_off[i] = excl;
        d_cur[i] = excl;
        float avg = d_avglog;
        float degf = (float)(v > 1 ? v : 1);
        float ld = logf(degf + 1.f);
        d_amp[i] = ld / avg;
        d_att[i] = avg / ld;
    }
}

__global__ void k_fill(const int* __restrict__ src, const int* __restrict__ dst) {
    int e = blockIdx.x * blockDim.x + threadIdx.x;
    if (e < NE) {
        int dn = dst[e];
        int p = atomicAdd(&d_cur[dn], 1);
        d_csr[p] = src[e];
    }
}

// ---------------- pre GEMM: [32 rows] x [64 -> 128]  (base|z) ----------------
__global__ __launch_bounds__(256) void k_pre(const float* __restrict__ X,
                                             const float* __restrict__ W,
                                             const float* __restrict__ B) {
    __shared__ float Xs[64][33];   // [k][row]
    __shared__ float Ws[64][132];  // [k][j]
    __shared__ float bs[64];
    int tid = threadIdx.x;
    int row0 = blockIdx.x * 32;
    for (int i = tid; i < 512; i += 256) {
        int r = i >> 4, kv = i & 15;
        int gr = row0 + r;
        float4 v = make_float4(0.f, 0.f, 0.f, 0.f);
        if (gr < NN) v = *(const float4*)(X + (size_t)gr * 64 + kv * 4);
        Xs[kv*4+0][r] = v.x; Xs[kv*4+1][r] = v.y; Xs[kv*4+2][r] = v.z; Xs[kv*4+3][r] = v.w;
    }
    for (int i = tid; i < 8192; i += 256) {
        int j = i >> 6, k = i & 63;
        Ws[k][j] = (j < 64) ? W[j * 128 + k] : W[(j - 64) * 128 + 64 + k];
    }
    if (tid < 64) bs[tid] = B[tid];
    __syncthreads();
    int tx = tid & 15, ty = tid >> 4;
    float acc[2][8];
    #pragma unroll
    for (int r = 0; r < 2; r++)
        #pragma unroll
        for (int j = 0; j < 8; j++) acc[r][j] = 0.f;
    #pragma unroll 4
    for (int k = 0; k < 64; k++) {
        float a0 = Xs[k][ty * 2 + 0];
        float a1 = Xs[k][ty * 2 + 1];
        float4 w0 = *(const float4*)&Ws[k][tx * 8];
        float4 w1 = *(const float4*)&Ws[k][tx * 8 + 4];
        float w[8] = {w0.x, w0.y, w0.z, w0.w, w1.x, w1.y, w1.z, w1.w};
        #pragma unroll
        for (int j = 0; j < 8; j++) { acc[0][j] += a0 * w[j]; acc[1][j] += a1 * w[j]; }
    }
    int j0 = tx * 8;
    #pragma unroll
    for (int r = 0; r < 2; r++) {
        int gr = row0 + ty * 2 + r;
        if (gr >= NN) continue;
        float o[8];
        #pragma unroll
        for (int j = 0; j < 8; j++) o[j] = acc[r][j] + ((j0 < 64) ? bs[j0 + j] : 0.f);
        *(float4*)(d_zb + (size_t)gr * 128 + j0) = make_float4(o[0], o[1], o[2], o[3]);
        *(float4*)(d_zb + (size_t)gr * 128 + j0 + 4) = make_float4(o[4], o[5], o[6], o[7]);
    }
}

// ---------------- aggregation: 1 warp per node ----------------
__global__ __launch_bounds__(256) void k_aggr() {
    int gw = (blockIdx.x * blockDim.x + threadIdx.x) >> 5;
    int lane = threadIdx.x & 31;
    if (gw >= NN) return;
    int beg = d_off[gw], end = d_off[gw + 1];
    float2 base = *(const float2*)(d_zb + (size_t)gw * 128 + lane * 2);
    float s1x = 0.f, s1y = 0.f, s2x = 0.f, s2y = 0.f;
    float mnx = INFINITY, mny = INFINITY, mxx = -INFINITY, mxy = -INFINITY;
    int e = beg;
    for (; e + 4 <= end; e += 4) {
        int i0 = d_csr[e], i1 = d_csr[e + 1], i2 = d_csr[e + 2], i3 = d_csr[e + 3];
        float2 z0 = *(const float2*)(d_zb + (size_t)i0 * 128 + 64 + lane * 2);
        float2 z1 = *(const float2*)(d_zb + (size_t)i1 * 128 + 64 + lane * 2);
        float2 z2 = *(const float2*)(d_zb + (size_t)i2 * 128 + 64 + lane * 2);
        float2 z3 = *(const float2*)(d_zb + (size_t)i3 * 128 + 64 + lane * 2);
        float mx0 = base.x + z0.x, my0 = base.y + z0.y;
        float mx1 = base.x + z1.x, my1 = base.y + z1.y;
        float mx2 = base.x + z2.x, my2 = base.y + z2.y;
        float mx3 = base.x + z3.x, my3 = base.y + z3.y;
        s1x += mx0 + mx1 + mx2 + mx3;
        s1y += my0 + my1 + my2 + my3;
        s2x += mx0*mx0 + mx1*mx1 + mx2*mx2 + mx3*mx3;
        s2y += my0*my0 + my1*my1 + my2*my2 + my3*my3;
        mnx = fminf(mnx, fminf(fminf(mx0, mx1), fminf(mx2, mx3)));
        mny = fminf(mny, fminf(fminf(my0, my1), fminf(my2, my3)));
        mxx = fmaxf(mxx, fmaxf(fmaxf(mx0, mx1), fmaxf(mx2, mx3)));
        mxy = fmaxf(mxy, fmaxf(fmaxf(my0, my1), fmaxf(my2, my3)));
    }
    for (; e < end; e++) {
        int s = d_csr[e];
        float2 z = *(const float2*)(d_zb + (size_t)s * 128 + 64 + lane * 2);
        float mx_ = base.x + z.x, my_ = base.y + z.y;
        s1x += mx_; s2x += mx_ * mx_; mnx = fminf(mnx, mx_); mxx = fmaxf(mxx, mx_);
        s1y += my_; s2y += my_ * my_; mny = fminf(mny, my_); mxy = fmaxf(mxy, my_);
    }
    int drI = end - beg;
    float deg = (float)(drI > 0 ? drI : 1);
    float meanx = s1x / deg, meany = s1y / deg;
    float stdx = sqrtf(fmaxf(s2x / deg - meanx * meanx, 0.f) + 1e-5f);
    float stdy = sqrtf(fmaxf(s2y / deg - meany * meany, 0.f) + 1e-5f);
    if (drI == 0) { mnx = 0.f; mny = 0.f; mxx = 0.f; mxy = 0.f; }
    float* a = d_aggr + (size_t)gw * 256;
    *(float2*)(a + lane * 2)       = make_float2(meanx, meany);
    *(float2*)(a + 64 + lane * 2)  = make_float2(mnx, mny);
    *(float2*)(a + 128 + lane * 2) = make_float2(mxx, mxy);
    *(float2*)(a + 192 + lane * 2) = make_float2(stdx, stdy);
}

// ---------------- post(832->64)+lin(64->64)+relu via 3xTF32 mma.sync ----------
// smem (bytes):
//   [0,256) bp   [256,512) bl   [512,1024) amp[128]   [1024,1536) att[128]
//   [2048, 20480)  Ahi : 128 x 36 u32
//   [20480,38912)  Alo : 128 x 36 u32
//   [38912,48128)  Bhi : 64 x 36 u32
//   [48128,57344)  Blo : 64 x 36 u32
#define POST_SMEM 57344

__global__ __launch_bounds__(256) void k_post_mma_sync(const float* __restrict__ X,
                                                       const float* __restrict__ Wp,
                                                       const float* __restrict__ bp,
                                                       const float* __restrict__ Wl,
                                                       const float* __restrict__ bl,
                                                       float* __restrict__ Xn) {
    extern __shared__ char smem[];
    float* s_bp  = (float*)(smem + 0);
    float* s_bl  = (float*)(smem + 256);
    float* s_amp = (float*)(smem + 512);
    float* s_att = (float*)(smem + 1024);
    uint32_t* sAh = (uint32_t*)(smem + 2048);
    uint32_t* sAl = (uint32_t*)(smem + 20480);
    uint32_t* sBh = (uint32_t*)(smem + 38912);
    uint32_t* sBl = (uint32_t*)(smem + 48128);

    int tid = threadIdx.x;
    int lane = tid & 31, wid = tid >> 5;
    int gid = lane >> 2, tq = lane & 3;
    int mrow = wid * 16;
    int row0 = blockIdx.x * 128;

    if (tid < 64) { s_bp[tid] = bp[tid]; s_bl[tid] = bl[tid]; }
    if (tid < 128) {
        int gr = row0 + tid;
        s_amp[tid] = (gr < NN) ? d_amp[gr] : 0.f;
        s_att[tid] = (gr < NN) ? d_att[gr] : 0.f;
    }

    float c[8][4];
    #pragma unroll
    for (int nt = 0; nt < 8; nt++)
        #pragma unroll
        for (int q = 0; q < 4; q++) c[nt][q] = 0.f;

    int rr = tid >> 3, f = tid & 7;   // staging: 32 rows/pass, 8 float4/row

    // ---------- phase 1: post GEMM, K=832 in 26 chunks of 32 ----------
    for (int ch = 0; ch < 26; ch++) {
        __syncthreads();
        int seg = ch >> 1, half = ch & 1;
        #pragma unroll
        for (int it = 0; it < 4; it++) {
            int r = rr + it * 32;
            int gr = row0 + r;
            float4 v = make_float4(0.f, 0.f, 0.f, 0.f);
            if (gr < NN) {
                if (seg == 0) {
                    v = *(const float4*)(X + (size_t)gr * 64 + half * 32 + f * 4);
                } else {
                    int cc = seg - 1;
                    v = *(const float4*)(d_aggr + (size_t)gr * 256 + (cc & 3) * 64 + half * 32 + f * 4);
                    if (cc >= 8)      { float s = s_att[r]; v.x *= s; v.y *= s; v.z *= s; v.w *= s; }
                    else if (cc >= 4) { float s = s_amp[r]; v.x *= s; v.y *= s; v.z *= s; v.w *= s; }
                }
            }
            int base = r * 36 + f * 4;
            uint32_t h, l;
            tf32_split(v.x, h, l); sAh[base + 0] = h; sAl[base + 0] = l;
            tf32_split(v.y, h, l); sAh[base + 1] = h; sAl[base + 1] = l;
            tf32_split(v.z, h, l); sAh[base + 2] = h; sAl[base + 2] = l;
            tf32_split(v.w, h, l); sAh[base + 3] = h; sAl[base + 3] = l;
        }
        #pragma unroll
        for (int i = 0; i < 2; i++) {
            int idx = tid + i * 256;
            int j = idx >> 3, fb = idx & 7;
            float4 w = *(const float4*)(Wp + (size_t)j * 832 + ch * 32 + fb * 4);
            int base = j * 36 + fb * 4;
            uint32_t h, l;
            tf32_split(w.x, h, l); sBh[base + 0] = h; sBl[base + 0] = l;
            tf32_split(w.y, h, l); sBh[base + 1] = h; sBl[base + 1] = l;
            tf32_split(w.z, h, l); sBh[base + 2] = h; sBl[base + 2] = l;
            tf32_split(w.w, h, l); sBh[base + 3] = h; sBl[base + 3] = l;
        }
        __syncthreads();
        #pragma unroll
        for (int ks = 0; ks < 4; ks++) {
            int k0 = ks * 8;
            int ra = (mrow + gid) * 36 + k0 + tq;
            int rb = (mrow + gid + 8) * 36 + k0 + tq;
            uint32_t ah0 = sAh[ra], ah1 = sAh[rb], ah2 = sAh[ra + 4], ah3 = sAh[rb + 4];
            uint32_t al0 = sAl[ra], al1 = sAl[rb], al2 = sAl[ra + 4], al3 = sAl[rb + 4];
            #pragma unroll
            for (int nt = 0; nt < 8; nt++) {
                int nb = (nt * 8 + gid) * 36 + k0 + tq;
                uint32_t bh0 = sBh[nb], bh1 = sBh[nb + 4];
                uint32_t bl0 = sBl[nb], bl1 = sBl[nb + 4];
                mma_tf32(c[nt][0], c[nt][1], c[nt][2], c[nt][3], ah0, ah1, ah2, ah3, bh0, bh1);
                mma_tf32(c[nt][0], c[nt][1], c[nt][2], c[nt][3], ah0, ah1, ah2, ah3, bl0, bl1);
                mma_tf32(c[nt][0], c[nt][1], c[nt][2], c[nt][3], al0, al1, al2, al3, bh0, bh1);
            }
        }
    }

    // ---------- phase 2: lin GEMM, K=64 in 2 chunks of 32 (reuse buffers) ----------
    float c2[8][4];
    #pragma unroll
    for (int nt = 0; nt < 8; nt++)
        #pragma unroll
        for (int q = 0; q < 4; q++) c2[nt][q] = 0.f;

    for (int ch2 = 0; ch2 < 2; ch2++) {
        __syncthreads();
        // stage A2 chunk from C fragments (+bias), cols [ch2*32, ch2*32+32)
        #pragma unroll
        for (int nt2 = 0; nt2 < 4; nt2++) {
            int nt = ch2 * 4 + nt2;
            int col = nt * 8 + 2 * tq;
            int lc = col - ch2 * 32;
            float v0 = c[nt][0] + s_bp[col];
            float v1 = c[nt][1] + s_bp[col + 1];
            float v2 = c[nt][2] + s_bp[col];
            float v3 = c[nt][3] + s_bp[col + 1];
            int r0 = (mrow + gid) * 36, r1 = (mrow + gid + 8) * 36;
            uint32_t h, l;
            tf32_split(v0, h, l); sAh[r0 + lc]     = h; sAl[r0 + lc]     = l;
            tf32_split(v1, h, l); sAh[r0 + lc + 1] = h; sAl[r0 + lc + 1] = l;
            tf32_split(v2, h, l); sAh[r1 + lc]     = h; sAl[r1 + lc]     = l;
            tf32_split(v3, h, l); sAh[r1 + lc + 1] = h; sAl[r1 + lc + 1] = l;
        }
        // stage B2 chunk from Wl, k range [ch2*32, ch2*32+32)
        #pragma unroll
        for (int i = 0; i < 2; i++) {
            int idx = tid + i * 256;
            int j = idx >> 3, fb = idx & 7;
            float4 w = *(const float4*)(Wl + (size_t)j * 64 + ch2 * 32 + fb * 4);
            int base = j * 36 + fb * 4;
            uint32_t h, l;
            tf32_split(w.x, h, l); sBh[base + 0] = h; sBl[base + 0] = l;
            tf32_split(w.y, h, l); sBh[base + 1] = h; sBl[base + 1] = l;
            tf32_split(w.z, h, l); sBh[base + 2] = h; sBl[base + 2] = l;
            tf32_split(w.w, h, l); sBh[base + 3] = h; sBl[base + 3] = l;
        }
        __syncthreads();
        #pragma unroll
        for (int ks = 0; ks < 4; ks++) {
            int k0 = ks * 8;
            int ra = (mrow + gid) * 36 + k0 + tq;
            int rb = (mrow + gid + 8) * 36 + k0 + tq;
            uint32_t ah0 = sAh[ra], ah1 = sAh[rb], ah2 = sAh[ra + 4], ah3 = sAh[rb + 4];
            uint32_t al0 = sAl[ra], al1 = sAl[rb], al2 = sAl[ra + 4], al3 = sAl[rb + 4];
            #pragma unroll
            for (int nt = 0; nt < 8; nt++) {
                int nb = (nt * 8 + gid) * 36 + k0 + tq;
                uint32_t bh0 = sBh[nb], bh1 = sBh[nb + 4];
                uint32_t bl0 = sBl[nb], bl1 = sBl[nb + 4];
                mma_tf32(c2[nt][0], c2[nt][1], c2[nt][2], c2[nt][3], ah0, ah1, ah2, ah3, bh0, bh1);
                mma_tf32(c2[nt][0], c2[nt][1], c2[nt][2], c2[nt][3], ah0, ah1, ah2, ah3, bl0, bl1);
                mma_tf32(c2[nt][0], c2[nt][1], c2[nt][2], c2[nt][3], al0, al1, al2, al3, bh0, bh1);
            }
        }
    }

    // epilogue: relu(C2 + bl) -> gmem
    int grow0 = row0 + mrow + gid;
    int grow1 = grow0 + 8;
    #pragma unroll
    for (int nt = 0; nt < 8; nt++) {
        int col = nt * 8 + 2 * tq;
        float bl0 = s_bl[col], bl1 = s_bl[col + 1];
        if (grow0 < NN) {
            float2 o = make_float2(fmaxf(c2[nt][0] + bl0, 0.f), fmaxf(c2[nt][1] + bl1, 0.f));
            *(float2*)(Xn + (size_t)grow0 * 64 + col) = o;
        }
        if (grow1 < NN) {
            float2 o = make_float2(fmaxf(c2[nt][2] + bl0, 0.f), fmaxf(c2[nt][3] + bl1, 0.f));
            *(float2*)(Xn + (size_t)grow1 * 64 + col) = o;
        }
    }
}

// ---------------- pooling + MLP ----------------
__global__ void k_pool(const float* __restrict__ X, const int* __restrict__ batch) {
    int idx = blockIdx.x * blockDim.x + threadIdx.x;
    int f = idx & 63;
    int chunk = idx >> 6;
    int n0 = chunk * 8;
    if (n0 >= NN) return;
    int ne = n0 + 8 < NN ? n0 + 8 : NN;
    int cg = batch[n0];
    float acc = 0.f;
    int cnt = 0;
    for (int n = n0; n < ne; n++) {
        int g = batch[n];
        if (g != cg) {
            atomicAdd(&d_pool[cg * 64 + f], acc);
            if (f == 0) atomicAdd(&d_cnt[cg], cnt);
            acc = 0.f; cnt = 0; cg = g;
        }
        acc += X[(size_t)n * 64 + f];
        cnt++;
    }
    atomicAdd(&d_pool[cg * 64 + f], acc);
    if (f == 0) atomicAdd(&d_cnt[cg], cnt);
}

__global__ void k_mlp(const float* __restrict__ W1, const float* __restrict__ b1,
                      const float* __restrict__ W2, const float* __restrict__ b2,
                      float* __restrict__ out) {
    __shared__ float gv[64], hv[64];
    int g = blockIdx.x, t = threadIdx.x;
    int c = d_cnt[g];
    float cntf = (float)(c > 1 ? c : 1);
    gv[t] = d_pool[g * 64 + t] / cntf;
    __syncthreads();
    float a = b1[t];
    #pragma unroll 8
    for (int k = 0; k < 64; k++) a += W1[t * 64 + k] * gv[k];
    hv[t] = fmaxf(a, 0.f);
    __syncthreads();
    if (t < 16) {
        float o = b2[t];
        #pragma unroll 8
        for (int k = 0; k < 64; k++) o += W2[t * 64 + k] * hv[k];
        out[g * 16 + t] = o;
    }
}

// ---------------- launch ----------------
extern "C" void kernel_launch(void* const* d_in, const int* in_sizes, int n_in,
                              void* d_out, int out_size) {
    const float* x      = (const float*)d_in[0];
    const int*   ei     = (const int*)d_in[1];
    const int*   batch  = (const int*)d_in[2];
    const float* pre_w  = (const float*)d_in[3];
    const float* pre_b  = (const float*)d_in[4];
    const float* post_w = (const float*)d_in[5];
    const float* post_b = (const float*)d_in[6];
    const float* lin_w  = (const float*)d_in[7];
    const float* lin_b  = (const float*)d_in[8];
    const float* mw1    = (const float*)d_in[9];
    const float* mb1    = (const float*)d_in[10];
    const float* mw2    = (const float*)d_in[11];
    const float* mb2    = (const float*)d_in[12];
    float* out = (float*)d_out;
    const int* srcp = ei;
    const int* dstp = ei + NE;

    void *pa, *pb;
    cudaGetSymbolAddress(&pa, d_xa);
    cudaGetSymbolAddress(&pb, d_xb);
    float* xa = (float*)pa;
    float* xb = (float*)pb;

    cudaFuncSetAttribute(k_post_mma_sync, cudaFuncAttributeMaxDynamicSharedMemorySize, POST_SMEM);

    k_init<<<(NN + 255) / 256, 256>>>();
    k_degree<<<(NE + 255) / 256, 256>>>(dstp);
    k_scan1<<<NB_SCAN, 256>>>();
    k_scan2<<<1, 256>>>();
    k_scan3<<<NB_SCAN, 256>>>();
    k_fill<<<(NE + 255) / 256, 256>>>(srcp, dstp);

    const float* cur = x;
    float* nxt = xa;
    for (int l = 0; l < 3; l++) {
        k_pre<<<(NN + 31) / 32, 256>>>(cur, pre_w + l * 64 * 128, pre_b + l * 64);
        k_aggr<<<(NN * 32 + 255) / 256, 256>>>();
        k_post_mma_sync<<<(NN + 127) / 128, 256, POST_SMEM>>>(
            cur, post_w + (size_t)l * 64 * 832, post_b + l * 64,
            lin_w + l * 64 * 64, lin_b + l * 64, nxt);
        cur = nxt;
        nxt = (nxt == xa) ? xb : xa;
    }
    k_pool<<<(((NN + 7) / 8) * 64 + 255) / 256, 256>>>(cur, batch);
    k_mlp<<<NG, 64>>>(mw1, mb1, mw2, mb2, out);
}

// round 6
// speedup vs baseline: 1.7572x; 1.1972x over previous
#include <cuda_runtime.h>
#include <cstdint>
#include <math.h>

#define NN 50000
#define NE 800000
#define NG 64
#define NB_SCAN 196   // ceil(NN/256)

// ---------------- scratch (static __device__, no allocs) ----------------
__device__ __align__(16) float d_zb[NN * 128];    // [base(64) | z(64)] per node
__device__ __align__(16) float d_aggr[NN * 256];  // [mean|min|max|std]
__device__ __align__(16) float d_xa[NN * 64];
__device__ __align__(16) float d_xb[NN * 64];
__device__ int   d_deg[NN];
__device__ int   d_off[NN + 1];
__device__ int   d_cur[NN];
__device__ int   d_csr[NE];
__device__ float d_amp[NN];
__device__ float d_att[NN];
__device__ float d_avglog;
__device__ float d_pool[NG * 64];
__device__ int   d_cnt[NG];
__device__ int   d_part[NB_SCAN];
__device__ float d_logpart[NB_SCAN];
__device__ int   d_boff[NB_SCAN];
// presplit tf32 hi/lo weights
__device__ __align__(16) uint32_t d_wph[3 * 64 * 832];
__device__ __align__(16) uint32_t d_wpl[3 * 64 * 832];
__device__ __align__(16) uint32_t d_pwh[3 * 128 * 64];
__device__ __align__(16) uint32_t d_pwl[3 * 128 * 64];
__device__ __align__(16) uint32_t d_lwh[3 * 64 * 64];
__device__ __align__(16) uint32_t d_lwl[3 * 64 * 64];

// ---------------- mma.sync tf32 helpers (sm_80+ baseline PTX) ----------
__device__ __forceinline__ uint32_t f2tf(float x) {
    uint32_t u;
    asm("cvt.rna.tf32.f32 %0, %1;" : "=r"(u) : "f"(x));
    return u;
}

__device__ __forceinline__ void tf32_split(float v, uint32_t& hi, uint32_t& lo) {
    uint32_t h = f2tf(v);
    hi = h;
    lo = f2tf(v - __uint_as_float(h));
}

__device__ __forceinline__ void mma_tf32(float& c0, float& c1, float& c2, float& c3,
                                         uint32_t a0, uint32_t a1, uint32_t a2, uint32_t a3,
                                         uint32_t b0, uint32_t b1) {
    asm volatile("mma.sync.aligned.m16n8k8.row.col.f32.tf32.tf32.f32 "
        "{%0,%1,%2,%3}, {%4,%5,%6,%7}, {%8,%9}, {%0,%1,%2,%3};"
        : "+f"(c0), "+f"(c1), "+f"(c2), "+f"(c3)
        : "r"(a0), "r"(a1), "r"(a2), "r"(a3), "r"(b0), "r"(b1));
}

// 3-term 3xTF32 accumulate
#define MMA3(C, ah0, ah1, ah2, ah3, al0, al1, al2, al3, bh0, bh1, bl0, bl1) do { \
    mma_tf32(C[0], C[1], C[2], C[3], ah0, ah1, ah2, ah3, bh0, bh1); \
    mma_tf32(C[0], C[1], C[2], C[3], ah0, ah1, ah2, ah3, bl0, bl1); \
    mma_tf32(C[0], C[1], C[2], C[3], al0, al1, al2, al3, bh0, bh1); \
} while (0)

// ---------------- setup kernels ----------------
__global__ void k_init() {
    int i = blockIdx.x * blockDim.x + threadIdx.x;
    if (i < NN) d_deg[i] = 0;
    if (i < NG * 64) d_pool[i] = 0.f;
    if (i < NG) d_cnt[i] = 0;
}

__global__ void k_degree(const int* __restrict__ dst) {
    int e = blockIdx.x * blockDim.x + threadIdx.x;
    if (e < NE) atomicAdd(&d_deg[dst[e]], 1);
}

// split all weights into tf32 hi/lo once
__global__ void k_splitw(const float* __restrict__ pre_w,
                         const float* __restrict__ post_w,
                         const float* __restrict__ lin_w) {
    int stride = gridDim.x * blockDim.x;
    int i0 = blockIdx.x * blockDim.x + threadIdx.x;
    for (int t = i0; t < 3 * 64 * 832; t += stride) {
        uint32_t h, l;
        tf32_split(post_w[t], h, l);
        d_wph[t] = h; d_wpl[t] = l;
    }
    for (int t = i0; t < 3 * 128 * 64; t += stride) {
        int l = t >> 13, r = t & 8191;
        int j = r >> 6, k = r & 63;
        int jj = j & 63, off = (j >= 64) ? 64 : 0;
        float v = pre_w[l * 8192 + jj * 128 + off + k];
        uint32_t h, lo;
        tf32_split(v, h, lo);
        d_pwh[t] = h; d_pwl[t] = lo;
    }
    for (int t = i0; t < 3 * 64 * 64; t += stride) {
        uint32_t h, l;
        tf32_split(lin_w[t], h, l);
        d_lwh[t] = h; d_lwl[t] = l;
    }
}

__global__ void k_scan1() {
    __shared__ int ssum[8];
    __shared__ float slog[8];
    int tid = threadIdx.x, lane = tid & 31, w = tid >> 5;
    int i = blockIdx.x * 256 + tid;
    int v = (i < NN) ? d_deg[i] : 0;
    float l = (i < NN) ? logf((float)v + 1.f) : 0.f;
    int s = v;
    #pragma unroll
    for (int d = 16; d; d >>= 1) {
        s += __shfl_xor_sync(0xffffffffu, s, d);
        l += __shfl_xor_sync(0xffffffffu, l, d);
    }
    if (lane == 0) { ssum[w] = s; slog[w] = l; }
    __syncthreads();
    if (tid == 0) {
        int t = 0; float lt = 0.f;
        #pragma unroll
        for (int k = 0; k < 8; k++) { t += ssum[k]; lt += slog[k]; }
        d_part[blockIdx.x] = t;
        d_logpart[blockIdx.x] = lt;
    }
}

__global__ void k_scan2() {
    __shared__ int ws[8];
    __shared__ float ls[8];
    int tid = threadIdx.x, lane = tid & 31, w = tid >> 5;
    int v = (tid < NB_SCAN) ? d_part[tid] : 0;
    float lg = (tid < NB_SCAN) ? d_logpart[tid] : 0.f;
    int x = v;
    #pragma unroll
    for (int d = 1; d < 32; d <<= 1) {
        int t = __shfl_up_sync(0xffffffffu, x, d);
        if (lane >= d) x += t;
    }
    #pragma unroll
    for (int d = 16; d; d >>= 1) lg += __shfl_xor_sync(0xffffffffu, lg, d);
    if (lane == 31) ws[w] = x;
    if (lane == 0) ls[w] = lg;
    __syncthreads();
    if (tid == 0) {
        int acc = 0;
        float lt = 0.f;
        #pragma unroll
        for (int k = 0; k < 8; k++) { int t = ws[k]; ws[k] = acc; acc += t; lt += ls[k]; }
        d_avglog = lt / (float)NN;
        d_off[NN] = NE;
    }
    __syncthreads();
    int excl = ws[w] + x - v;
    if (tid < NB_SCAN) d_boff[tid] = excl;
}

__global__ void k_scan3() {
    __shared__ int ws[8];
    int tid = threadIdx.x, lane = tid & 31, w = tid >> 5;
    int i = blockIdx.x * 256 + tid;
    int v = (i < NN) ? d_deg[i] : 0;
    int x = v;
    #pragma unroll
    for (int d = 1; d < 32; d <<= 1) {
        int t = __shfl_up_sync(0xffffffffu, x, d);
        if (lane >= d) x += t;
    }
    if (lane == 31) ws[w] = x;
    __syncthreads();
    if (tid == 0) {
        int acc = 0;
        #pragma unroll
        for (int k = 0; k < 8; k++) { int t = ws[k]; ws[k] = acc; acc += t; }
    }
    __syncthreads();
    int excl = d_boff[blockIdx.x] + ws[w] + x - v;
    if (i < NN) {
        d_off[i] = excl;
        d_cur[i] = excl;
        float avg = d_avglog;
        float degf = (float)(v > 1 ? v : 1);
        float ld = logf(degf + 1.f);
        d_amp[i] = ld / avg;
        d_att[i] = avg / ld;
    }
}

__global__ void k_fill(const int* __restrict__ src, const int* __restrict__ dst) {
    int e = blockIdx.x * blockDim.x + threadIdx.x;
    if (e < NE) {
        int dn = dst[e];
        int p = atomicAdd(&d_cur[dn], 1);
        d_csr[p] = src[e];
    }
}

// ---------------- pre GEMM via 3xTF32 mma: [128 rows] x [64 -> 128] ----------
// smem: [0,256) bias | [2048,20480) Ah 128x36 | [20480,38912) Al
//       [38912,57344) Bh 128x36 | [57344,75776) Bl
#define PRE_SMEM 75776

__global__ __launch_bounds__(256) void k_pre_mma(const float* __restrict__ X,
                                                 const uint32_t* __restrict__ pwh,
                                                 const uint32_t* __restrict__ pwl,
                                                 const float* __restrict__ B) {
    extern __shared__ char smem[];
    float* s_bias = (float*)(smem + 0);
    uint32_t* sAh = (uint32_t*)(smem + 2048);
    uint32_t* sAl = (uint32_t*)(smem + 20480);
    uint32_t* sBh = (uint32_t*)(smem + 38912);
    uint32_t* sBl = (uint32_t*)(smem + 57344);

    int tid = threadIdx.x;
    int lane = tid & 31, wid = tid >> 5;
    int gid = lane >> 2, tq = lane & 3;
    int mrow = wid * 16;
    int row0 = blockIdx.x * 128;
    if (tid < 64) s_bias[tid] = B[tid];

    float c[16][4];
    #pragma unroll
    for (int nt = 0; nt < 16; nt++)
        #pragma unroll
        for (int q = 0; q < 4; q++) c[nt][q] = 0.f;

    int rr = tid >> 3, f = tid & 7;

    for (int ch = 0; ch < 2; ch++) {
        __syncthreads();
        // A: 128 rows x 32 k, split
        #pragma unroll
        for (int it = 0; it < 4; it++) {
            int r = rr + it * 32;
            int gr = row0 + r;
            float4 v = make_float4(0.f, 0.f, 0.f, 0.f);
            if (gr < NN) v = *(const float4*)(X + (size_t)gr * 64 + ch * 32 + f * 4);
            uint32_t h0, l0, h1, l1, h2, l2, h3, l3;
            tf32_split(v.x, h0, l0); tf32_split(v.y, h1, l1);
            tf32_split(v.z, h2, l2); tf32_split(v.w, h3, l3);
            int base = r * 36 + f * 4;
            *(uint4*)&sAh[base] = make_uint4(h0, h1, h2, h3);
            *(uint4*)&sAl[base] = make_uint4(l0, l1, l2, l3);
        }
        // B: 128 out-rows x 32 k, straight copy of presplit
        #pragma unroll
        for (int it = 0; it < 4; it++) {
            int idx = tid + it * 256;
            int j = idx >> 3, fb = idx & 7;
            int src = j * 64 + ch * 32 + fb * 4;
            uint4 h = *(const uint4*)(pwh + src);
            uint4 l = *(const uint4*)(pwl + src);
            int dst = j * 36 + fb * 4;
            *(uint4*)&sBh[dst] = h;
            *(uint4*)&sBl[dst] = l;
        }
        __syncthreads();
        #pragma unroll
        for (int ks = 0; ks < 4; ks++) {
            int k0 = ks * 8;
            int ra = (mrow + gid) * 36 + k0 + tq;
            int rb = (mrow + gid + 8) * 36 + k0 + tq;
            uint32_t ah0 = sAh[ra], ah1 = sAh[rb], ah2 = sAh[ra + 4], ah3 = sAh[rb + 4];
            uint32_t al0 = sAl[ra], al1 = sAl[rb], al2 = sAl[ra + 4], al3 = sAl[rb + 4];
            #pragma unroll
            for (int nt = 0; nt < 16; nt++) {
                int nb = (nt * 8 + gid) * 36 + k0 + tq;
                uint32_t bh0 = sBh[nb], bh1 = sBh[nb + 4];
                uint32_t bl0 = sBl[nb], bl1 = sBl[nb + 4];
                MMA3(c[nt], ah0, ah1, ah2, ah3, al0, al1, al2, al3, bh0, bh1, bl0, bl1);
            }
        }
    }
    // epilogue: +bias on cols<64, store [base|z] to d_zb
    int grow0 = row0 + mrow + gid;
    int grow1 = grow0 + 8;
    #pragma unroll
    for (int nt = 0; nt < 16; nt++) {
        int col = nt * 8 + 2 * tq;
        float b0 = (col < 64) ? s_bias[col] : 0.f;
        float b1 = (col < 64) ? s_bias[col + 1] : 0.f;
        if (grow0 < NN)
            *(float2*)(d_zb + (size_t)grow0 * 128 + col) = make_float2(c[nt][0] + b0, c[nt][1] + b1);
        if (grow1 < NN)
            *(float2*)(d_zb + (size_t)grow1 * 128 + col) = make_float2(c[nt][2] + b0, c[nt][3] + b1);
    }
}

// ---------------- aggregation: 1 warp per node ----------------
__global__ __launch_bounds__(256) void k_aggr() {
    int gw = (blockIdx.x * blockDim.x + threadIdx.x) >> 5;
    int lane = threadIdx.x & 31;
    if (gw >= NN) return;
    int beg = d_off[gw], end = d_off[gw + 1];
    float2 base = *(const float2*)(d_zb + (size_t)gw * 128 + lane * 2);
    float s1x = 0.f, s1y = 0.f, s2x = 0.f, s2y = 0.f;
    float mnx = INFINITY, mny = INFINITY, mxx = -INFINITY, mxy = -INFINITY;
    int e = beg;
    for (; e + 4 <= end; e += 4) {
        int i0 = d_csr[e], i1 = d_csr[e + 1], i2 = d_csr[e + 2], i3 = d_csr[e + 3];
        float2 z0 = *(const float2*)(d_zb + (size_t)i0 * 128 + 64 + lane * 2);
        float2 z1 = *(const float2*)(d_zb + (size_t)i1 * 128 + 64 + lane * 2);
        float2 z2 = *(const float2*)(d_zb + (size_t)i2 * 128 + 64 + lane * 2);
        float2 z3 = *(const float2*)(d_zb + (size_t)i3 * 128 + 64 + lane * 2);
        float mx0 = base.x + z0.x, my0 = base.y + z0.y;
        float mx1 = base.x + z1.x, my1 = base.y + z1.y;
        float mx2 = base.x + z2.x, my2 = base.y + z2.y;
        float mx3 = base.x + z3.x, my3 = base.y + z3.y;
        s1x += mx0 + mx1 + mx2 + mx3;
        s1y += my0 + my1 + my2 + my3;
        s2x += mx0*mx0 + mx1*mx1 + mx2*mx2 + mx3*mx3;
        s2y += my0*my0 + my1*my1 + my2*my2 + my3*my3;
        mnx = fminf(mnx, fminf(fminf(mx0, mx1), fminf(mx2, mx3)));
        mny = fminf(mny, fminf(fminf(my0, my1), fminf(my2, my3)));
        mxx = fmaxf(mxx, fmaxf(fmaxf(mx0, mx1), fmaxf(mx2, mx3)));
        mxy = fmaxf(mxy, fmaxf(fmaxf(my0, my1), fmaxf(my2, my3)));
    }
    for (; e < end; e++) {
        int s = d_csr[e];
        float2 z = *(const float2*)(d_zb + (size_t)s * 128 + 64 + lane * 2);
        float mx_ = base.x + z.x, my_ = base.y + z.y;
        s1x += mx_; s2x += mx_ * mx_; mnx = fminf(mnx, mx_); mxx = fmaxf(mxx, mx_);
        s1y += my_; s2y += my_ * my_; mny = fminf(mny, my_); mxy = fmaxf(mxy, my_);
    }
    int drI = end - beg;
    float deg = (float)(drI > 0 ? drI : 1);
    float meanx = s1x / deg, meany = s1y / deg;
    float stdx = sqrtf(fmaxf(s2x / deg - meanx * meanx, 0.f) + 1e-5f);
    float stdy = sqrtf(fmaxf(s2y / deg - meany * meany, 0.f) + 1e-5f);
    if (drI == 0) { mnx = 0.f; mny = 0.f; mxx = 0.f; mxy = 0.f; }
    float* a = d_aggr + (size_t)gw * 256;
    *(float2*)(a + lane * 2)       = make_float2(meanx, meany);
    *(float2*)(a + 64 + lane * 2)  = make_float2(mnx, mny);
    *(float2*)(a + 128 + lane * 2) = make_float2(mxx, mxy);
    *(float2*)(a + 192 + lane * 2) = make_float2(stdx, stdy);
}

// ---------------- post+lin via 3xTF32 mma, linearity-restructured ----------
// out1 = x@W0 + aggr@W1 + amp*(aggr@W2) + att*(aggr@W3) + bp; out = relu(out1@Wl + bl)
// smem: [0,256) bp | [256,512) bl | [512,1024) amp | [1024,1536) att
//  [2048,20480) Ah 128x36 | [20480,38912) Al
//  [38912,66560) Bh 3x64x36 | [66560,94208) Bl
#define POST_SMEM 94208

__global__ __launch_bounds__(256) void k_post_mma_sync(const float* __restrict__ X,
                                                       const uint32_t* __restrict__ wph,
                                                       const uint32_t* __restrict__ wpl,
                                                       const float* __restrict__ bp,
                                                       const uint32_t* __restrict__ lwh,
                                                       const uint32_t* __restrict__ lwl,
                                                       const float* __restrict__ bl,
                                                       float* __restrict__ Xn) {
    extern __shared__ char smem[];
    float* s_bp  = (float*)(smem + 0);
    float* s_bl  = (float*)(smem + 256);
    float* s_amp = (float*)(smem + 512);
    float* s_att = (float*)(smem + 1024);
    uint32_t* sAh = (uint32_t*)(smem + 2048);
    uint32_t* sAl = (uint32_t*)(smem + 20480);
    uint32_t* sBh = (uint32_t*)(smem + 38912);   // 3 mats, stride 2304 u32
    uint32_t* sBl = (uint32_t*)(smem + 66560);

    int tid = threadIdx.x;
    int lane = tid & 31, wid = tid >> 5;
    int gid = lane >> 2, tq = lane & 3;
    int mrow = wid * 16;
    int row0 = blockIdx.x * 128;

    if (tid < 64) { s_bp[tid] = bp[tid]; s_bl[tid] = bl[tid]; }
    if (tid < 128) {
        int gr = row0 + tid;
        s_amp[tid] = (gr < NN) ? d_amp[gr] : 0.f;
        s_att[tid] = (gr < NN) ? d_att[gr] : 0.f;
    }

    float c1[8][4], c2[8][4], c3[8][4];
    #pragma unroll
    for (int nt = 0; nt < 8; nt++)
        #pragma unroll
        for (int q = 0; q < 4; q++) { c1[nt][q] = 0.f; c2[nt][q] = 0.f; c3[nt][q] = 0.f; }

    int rr = tid >> 3, f = tid & 7;

    // ---------- phase 1: 10 A-chunks (2 x, 8 aggr) ----------
    for (int ch = 0; ch < 10; ch++) {
        __syncthreads();
        bool isX = (ch < 2);
        // stage A chunk (split)
        #pragma unroll
        for (int it = 0; it < 4; it++) {
            int r = rr + it * 32;
            int gr = row0 + r;
            float4 v = make_float4(0.f, 0.f, 0.f, 0.f);
            if (gr < NN) {
                if (isX) v = *(const float4*)(X + (size_t)gr * 64 + ch * 32 + f * 4);
                else     v = *(const float4*)(d_aggr + (size_t)gr * 256 + (ch - 2) * 32 + f * 4);
            }
            uint32_t h0, l0, h1, l1, h2, l2, h3, l3;
            tf32_split(v.x, h0, l0); tf32_split(v.y, h1, l1);
            tf32_split(v.z, h2, l2); tf32_split(v.w, h3, l3);
            int base = r * 36 + f * 4;
            *(uint4*)&sAh[base] = make_uint4(h0, h1, h2, h3);
            *(uint4*)&sAl[base] = make_uint4(l0, l1, l2, l3);
        }
        // stage B chunk(s): straight copies of presplit Wp
        if (isX) {
            #pragma unroll
            for (int i = 0; i < 2; i++) {
                int idx = tid + i * 256;
                int j = idx >> 3, fb = idx & 7;
                int src = j * 832 + ch * 32 + fb * 4;
                *(uint4*)&sBh[j * 36 + fb * 4] = *(const uint4*)(wph + src);
                *(uint4*)&sBl[j * 36 + fb * 4] = *(const uint4*)(wpl + src);
            }
        } else {
            int ca = ch - 2;
            #pragma unroll
            for (int m = 0; m < 3; m++) {
                int koff = 64 + m * 256 + ca * 32;
                #pragma unroll
                for (int i = 0; i < 2; i++) {
                    int idx = tid + i * 256;
                    int j = idx >> 3, fb = idx & 7;
                    int src = j * 832 + koff + fb * 4;
                    int dst = m * 2304 + j * 36 + fb * 4;
                    *(uint4*)&sBh[dst] = *(const uint4*)(wph + src);
                    *(uint4*)&sBl[dst] = *(const uint4*)(wpl + src);
                }
            }
        }
        __syncthreads();
        #pragma unroll
        for (int ks = 0; ks < 4; ks++) {
            int k0 = ks * 8;
            int ra = (mrow + gid) * 36 + k0 + tq;
            int rb = (mrow + gid + 8) * 36 + k0 + tq;
            uint32_t ah0 = sAh[ra], ah1 = sAh[rb], ah2 = sAh[ra + 4], ah3 = sAh[rb + 4];
            uint32_t al0 = sAl[ra], al1 = sAl[rb], al2 = sAl[ra + 4], al3 = sAl[rb + 4];
            if (isX) {
                #pragma unroll
                for (int nt = 0; nt < 8; nt++) {
                    int nb = (nt * 8 + gid) * 36 + k0 + tq;
                    uint32_t bh0 = sBh[nb], bh1 = sBh[nb + 4];
                    uint32_t bl0 = sBl[nb], bl1 = sBl[nb + 4];
                    MMA3(c1[nt], ah0, ah1, ah2, ah3, al0, al1, al2, al3, bh0, bh1, bl0, bl1);
                }
            } else {
                #pragma unroll
                for (int nt = 0; nt < 8; nt++) {
                    int nb = (nt * 8 + gid) * 36 + k0 + tq;
                    uint32_t bh0 = sBh[nb], bh1 = sBh[nb + 4];
                    uint32_t bl0 = sBl[nb], bl1 = sBl[nb + 4];
                    MMA3(c1[nt], ah0, ah1, ah2, ah3, al0, al1, al2, al3, bh0, bh1, bl0, bl1);
                    bh0 = sBh[nb + 2304]; bh1 = sBh[nb + 2304 + 4];
                    bl0 = sBl[nb + 2304]; bl1 = sBl[nb + 2304 + 4];
                    MMA3(c2[nt], ah0, ah1, ah2, ah3, al0, al1, al2, al3, bh0, bh1, bl0, bl1);
                    bh0 = sBh[nb + 4608]; bh1 = sBh[nb + 4608 + 4];
                    bl0 = sBl[nb + 4608]; bl1 = sBl[nb + 4608 + 4];
                    MMA3(c3[nt], ah0, ah1, ah2, ah3, al0, al1, al2, al3, bh0, bh1, bl0, bl1);
                }
            }
        }
    }

    // combine in-place into c1: c1 + amp*c2 + att*c3 + bp
    {
        float a0 = s_amp[mrow + gid], t0 = s_att[mrow + gid];
        float a1 = s_amp[mrow + gid + 8], t1 = s_att[mrow + gid + 8];
        #pragma unroll
        for (int nt = 0; nt < 8; nt++) {
            int col = nt * 8 + 2 * tq;
            c1[nt][0] += a0 * c2[nt][0] + t0 * c3[nt][0] + s_bp[col];
            c1[nt][1] += a0 * c2[nt][1] + t0 * c3[nt][1] + s_bp[col + 1];
            c1[nt][2] += a1 * c2[nt][2] + t1 * c3[nt][2] + s_bp[col];
            c1[nt][3] += a1 * c2[nt][3] + t1 * c3[nt][3] + s_bp[col + 1];
        }
    }

    // ---------- phase 2: lin GEMM, K=64 in 2 chunks of 32 ----------
    #pragma unroll
    for (int nt = 0; nt < 8; nt++)
        #pragma unroll
        for (int q = 0; q < 4; q++) c3[nt][q] = 0.f;

    for (int ch2 = 0; ch2 < 2; ch2++) {
        __syncthreads();
        #pragma unroll
        for (int nt2 = 0; nt2 < 4; nt2++) {
            int nt = ch2 * 4 + nt2;
            int col = nt * 8 + 2 * tq;
            int lc = col - ch2 * 32;
            int r0 = (mrow + gid) * 36, r1 = (mrow + gid + 8) * 36;
            uint32_t h, l;
            tf32_split(c1[nt][0], h, l); sAh[r0 + lc]     = h; sAl[r0 + lc]     = l;
            tf32_split(c1[nt][1], h, l); sAh[r0 + lc + 1] = h; sAl[r0 + lc + 1] = l;
            tf32_split(c1[nt][2], h, l); sAh[r1 + lc]     = h; sAl[r1 + lc]     = l;
            tf32_split(c1[nt][3], h, l); sAh[r1 + lc + 1] = h; sAl[r1 + lc + 1] = l;
        }
        #pragma unroll
        for (int i = 0; i < 2; i++) {
            int idx = tid + i * 256;
            int j = idx >> 3, fb = idx & 7;
            int src = j * 64 + ch2 * 32 + fb * 4;
            *(uint4*)&sBh[j * 36 + fb * 4] = *(const uint4*)(lwh + src);
            *(uint4*)&sBl[j * 36 + fb * 4] = *(const uint4*)(lwl + src);
        }
        __syncthreads();
        #pragma unroll
        for (int ks = 0; ks < 4; ks++) {
            int k0 = ks * 8;
            int ra = (mrow + gid) * 36 + k0 + tq;
            int rb = (mrow + gid + 8) * 36 + k0 + tq;
            uint32_t ah0 = sAh[ra], ah1 = sAh[rb], ah2 = sAh[ra + 4], ah3 = sAh[rb + 4];
            uint32_t al0 = sAl[ra], al1 = sAl[rb], al2 = sAl[ra + 4], al3 = sAl[rb + 4];
            #pragma unroll
            for (int nt = 0; nt < 8; nt++) {
                int nb = (nt * 8 + gid) * 36 + k0 + tq;
                uint32_t bh0 = sBh[nb], bh1 = sBh[nb + 4];
                uint32_t bl0 = sBl[nb], bl1 = sBl[nb + 4];
                MMA3(c3[nt], ah0, ah1, ah2, ah3, al0, al1, al2, al3, bh0, bh1, bl0, bl1);
            }
        }
    }

    // epilogue: relu(c3 + bl) -> gmem
    int grow0 = row0 + mrow + gid;
    int grow1 = grow0 + 8;
    #pragma unroll
    for (int nt = 0; nt < 8; nt++) {
        int col = nt * 8 + 2 * tq;
        float bl0 = s_bl[col], bl1 = s_bl[col + 1];
        if (grow0 < NN) {
            float2 o = make_float2(fmaxf(c3[nt][0] + bl0, 0.f), fmaxf(c3[nt][1] + bl1, 0.f));
            *(float2*)(Xn + (size_t)grow0 * 64 + col) = o;
        }
        if (grow1 < NN) {
            float2 o = make_float2(fmaxf(c3[nt][2] + bl0, 0.f), fmaxf(c3[nt][3] + bl1, 0.f));
            *(float2*)(Xn + (size_t)grow1 * 64 + col) = o;
        }
    }
}

// ---------------- pooling + MLP ----------------
__global__ void k_pool(const float* __restrict__ X, const int* __restrict__ batch) {
    int idx = blockIdx.x * blockDim.x + threadIdx.x;
    int f = idx & 63;
    int chunk = idx >> 6;
    int n0 = chunk * 8;
    if (n0 >= NN) return;
    int ne = n0 + 8 < NN ? n0 + 8 : NN;
    int cg = batch[n0];
    float acc = 0.f;
    int cnt = 0;
    for (int n = n0; n < ne; n++) {
        int g = batch[n];
        if (g != cg) {
            atomicAdd(&d_pool[cg * 64 + f], acc);
            if (f == 0) atomicAdd(&d_cnt[cg], cnt);
            acc = 0.f; cnt = 0; cg = g;
        }
        acc += X[(size_t)n * 64 + f];
        cnt++;
    }
    atomicAdd(&d_pool[cg * 64 + f], acc);
    if (f == 0) atomicAdd(&d_cnt[cg], cnt);
}

__global__ void k_mlp(const float* __restrict__ W1, const float* __restrict__ b1,
                      const float* __restrict__ W2, const float* __restrict__ b2,
                      float* __restrict__ out) {
    __shared__ float gv[64], hv[64];
    int g = blockIdx.x, t = threadIdx.x;
    int c = d_cnt[g];
    float cntf = (float)(c > 1 ? c : 1);
    gv[t] = d_pool[g * 64 + t] / cntf;
    __syncthreads();
    float a = b1[t];
    #pragma unroll 8
    for (int k = 0; k < 64; k++) a += W1[t * 64 + k] * gv[k];
    hv[t] = fmaxf(a, 0.f);
    __syncthreads();
    if (t < 16) {
        float o = b2[t];
        #pragma unroll 8
        for (int k = 0; k < 64; k++) o += W2[t * 64 + k] * hv[k];
        out[g * 16 + t] = o;
    }
}

// ---------------- launch ----------------
extern "C" void kernel_launch(void* const* d_in, const int* in_sizes, int n_in,
                              void* d_out, int out_size) {
    const float* x      = (const float*)d_in[0];
    const int*   ei     = (const int*)d_in[1];
    const int*   batch  = (const int*)d_in[2];
    const float* pre_w  = (const float*)d_in[3];
    const float* pre_b  = (const float*)d_in[4];
    const float* post_w = (const float*)d_in[5];
    const float* post_b = (const float*)d_in[6];
    const float* lin_w  = (const float*)d_in[7];
    const float* lin_b  = (const float*)d_in[8];
    const float* mw1    = (const float*)d_in[9];
    const float* mb1    = (const float*)d_in[10];
    const float* mw2    = (const float*)d_in[11];
    const float* mb2    = (const float*)d_in[12];
    float* out = (float*)d_out;
    const int* srcp = ei;
    const int* dstp = ei + NE;

    void *pa, *pb, *pw;
    cudaGetSymbolAddress(&pa, d_xa);
    cudaGetSymbolAddress(&pb, d_xb);
    float* xa = (float*)pa;
    float* xb = (float*)pb;
    uint32_t *wph, *wpl, *pwh, *pwl, *lwh, *lwl;
    cudaGetSymbolAddress(&pw, d_wph); wph = (uint32_t*)pw;
    cudaGetSymbolAddress(&pw, d_wpl); wpl = (uint32_t*)pw;
    cudaGetSymbolAddress(&pw, d_pwh); pwh = (uint32_t*)pw;
    cudaGetSymbolAddress(&pw, d_pwl); pwl = (uint32_t*)pw;
    cudaGetSymbolAddress(&pw, d_lwh); lwh = (uint32_t*)pw;
    cudaGetSymbolAddress(&pw, d_lwl); lwl = (uint32_t*)pw;

    cudaFuncSetAttribute(k_post_mma_sync, cudaFuncAttributeMaxDynamicSharedMemorySize, POST_SMEM);
    cudaFuncSetAttribute(k_pre_mma, cudaFuncAttributeMaxDynamicSharedMemorySize, PRE_SMEM);

    k_init<<<(NN + 255) / 256, 256>>>();
    k_splitw<<<312, 256>>>(pre_w, post_w, lin_w);
    k_degree<<<(NE + 255) / 256, 256>>>(dstp);
    k_scan1<<<NB_SCAN, 256>>>();
    k_scan2<<<1, 256>>>();
    k_scan3<<<NB_SCAN, 256>>>();
    k_fill<<<(NE + 255) / 256, 256>>>(srcp, dstp);

    const float* cur = x;
    float* nxt = xa;
    for (int l = 0; l < 3; l++) {
        k_pre_mma<<<(NN + 127) / 128, 256, PRE_SMEM>>>(cur, pwh + l * 8192, pwl + l * 8192,
                                                       pre_b + l * 64);
        k_aggr<<<(NN * 32 + 255) / 256, 256>>>();
        k_post_mma_sync<<<(NN + 127) / 128, 256, POST_SMEM>>>(
            cur, wph + l * 53248, wpl + l * 53248, post_b + l * 64,
            lwh + l * 4096, lwl + l * 4096, lin_b + l * 64, nxt);
        cur = nxt;
        nxt = (nxt == xa) ? xb : xa;
    }
    k_pool<<<(((NN + 7) / 8) * 64 + 255) / 256, 256>>>(cur, batch);
    k_mlp<<<NG, 64>>>(mw1, mb1, mw2, mb2, out);
}